// round 5
// baseline (speedup 1.0000x reference)
#include <cuda_runtime.h>
#include <cstdint>

// Problem constants
#define BB 512
#define VV 32768
#define CC 16
#define SS 4            // B-splits
#define TT 256          // threads per block
#define BPER (BB / SS)  // 128 samples per split

// EMA coefficient: 1 - MOMENTUM = 2/(STEPS_PER_EPOCH+1)
#define ALPHA ((float)(2.0 / 1001.0))

// Partial sums scratch: [S][C][V] fp32 = 8 MB (device global — no allocation)
__device__ float g_partials[SS * CC * VV];

// ---------------------------------------------------------------------------
// Stage 1: accumulate |sparse[b,v] * W_eff[b,v,labels[b]]| into per-split,
// per-class partial sums. Grid: (V/TT, SS). Each thread owns one v.
// ---------------------------------------------------------------------------
__global__ void __launch_bounds__(TT)
attr_accumulate_kernel(const float* __restrict__ sparse,
                       const float* __restrict__ W,
                       const int* __restrict__ labels)
{
    __shared__ float acc[CC * TT];   // acc[c*TT + tid] — conflict-free columns
    __shared__ int   lab[BPER];

    const int tid = threadIdx.x;
    const int v   = blockIdx.x * TT + tid;
    const int sb  = blockIdx.y;

    #pragma unroll
    for (int i = 0; i < CC; ++i)
        acc[i * TT + tid] = 0.0f;

    if (tid < BPER)
        lab[tid] = labels[sb * BPER + tid];
    __syncthreads();

    const float* __restrict__ spv = sparse + (size_t)sb * BPER * VV + v;
    const float* __restrict__ Wv  = W + ((size_t)sb * BPER * VV + (size_t)v) * CC;

    // Unroll-by-8: batch 16 independent global loads per thread ahead of the
    // (possibly aliasing) shared-memory read-modify-write chain.
    for (int b0 = 0; b0 < BPER; b0 += 8) {
        float sv[8], wv[8];
        int   lv[8];
        #pragma unroll
        for (int i = 0; i < 8; ++i) {
            const int b = b0 + i;
            lv[i] = lab[b];
            sv[i] = spv[(size_t)b * VV];
            wv[i] = Wv[(size_t)b * VV * CC + lv[i]];
        }
        #pragma unroll
        for (int i = 0; i < 8; ++i) {
            acc[lv[i] * TT + tid] += fabsf(sv[i] * wv[i]);
        }
    }

    // Each thread wrote only its own smem column — no sync needed.
    float* __restrict__ part = g_partials + (size_t)sb * CC * VV + v;
    #pragma unroll
    for (int c = 0; c < CC; ++c)
        part[(size_t)c * VV] = acc[c * TT + tid];
}

// ---------------------------------------------------------------------------
// Stage 2: reduce the S partials, compute per-class means, apply
// EMA / fresh-copy / no-op branches. Grid: V/TT. Each thread owns one v.
// initialized is int32 (harness widens numpy bool -> int32).
// ---------------------------------------------------------------------------
__global__ void __launch_bounds__(TT)
centroid_finalize_kernel(const float* __restrict__ centroids,
                         const int* __restrict__ labels,
                         const int* __restrict__ initialized,
                         float* __restrict__ out)
{
    __shared__ int cnt[CC];
    const int tid = threadIdx.x;

    if (tid < CC) cnt[tid] = 0;
    __syncthreads();
    for (int b = tid; b < BB; b += TT)
        atomicAdd(&cnt[labels[b]], 1);
    __syncthreads();

    const int v = blockIdx.x * TT + tid;

    #pragma unroll
    for (int c = 0; c < CC; ++c) {
        float sum = 0.0f;
        #pragma unroll
        for (int s = 0; s < SS; ++s)
            sum += g_partials[((size_t)s * CC + c) * VV + v];

        const int   n    = cnt[c];
        const float cen  = centroids[(size_t)c * VV + v];
        const float mean = sum / fmaxf((float)n, 1.0f);

        float o;
        if (n > 0)
            o = (initialized[c] != 0) ? (cen + ALPHA * (mean - cen)) : mean;
        else
            o = cen;

        out[(size_t)c * VV + v] = o;
    }
}

// ---------------------------------------------------------------------------
// Launch: graph-capturable, allocation-free.
// Inputs are identified BY ELEMENT COUNT (robust to metadata ordering):
//   W_eff       f32[B,V,C] -> 268435456 elems
//   sparse_vec  f32[B,V]   ->  16777216 elems
//   centroids   f32[C,V]   ->    524288 elems
//   labels      i32[B]     ->       512 elems
//   initialized i32[C]     ->        16 elems (bool widened to int32)
// Output: f32[C,V].
// ---------------------------------------------------------------------------
extern "C" void kernel_launch(void* const* d_in, const int* in_sizes, int n_in,
                              void* d_out, int out_size)
{
    const float* sparse    = nullptr;
    const float* W         = nullptr;
    const int*   labels    = nullptr;
    const float* centroids = nullptr;
    const int*   init      = nullptr;
    float*       out       = (float*)d_out;

    for (int i = 0; i < n_in; ++i) {
        switch (in_sizes[i]) {
            case BB * VV:            sparse    = (const float*)d_in[i]; break; // 16777216
            case BB:                 labels    = (const int*)d_in[i];   break; // 512
            case CC * VV:            centroids = (const float*)d_in[i]; break; // 524288
            case CC:                 init      = (const int*)d_in[i];   break; // 16
            default:                 W         = (const float*)d_in[i]; break; // 268435456
        }
    }

    dim3 g1(VV / TT, SS);
    attr_accumulate_kernel<<<g1, TT>>>(sparse, W, labels);

    centroid_finalize_kernel<<<VV / TT, TT>>>(centroids, labels, init, out);
}

// round 6
// speedup vs baseline: 1.0289x; 1.0289x over previous
#include <cuda_runtime.h>
#include <cstdint>

// Problem constants
#define BB 512
#define VV 32768
#define CC 16
#define SS 8            // B-splits
#define TT 256          // threads per block
#define BPER (BB / SS)  // 64 samples per split

// EMA coefficient: 1 - MOMENTUM = 2/(STEPS_PER_EPOCH+1)
#define ALPHA ((float)(2.0 / 1001.0))

// Scratch (device globals — allocation-free):
__device__ float g_partials[SS * CC * VV];  // [S][C][V] fp32 = 16 MB
__device__ int   g_perm[BB];                // class-sorted sample indices, per split
__device__ int   g_cnt[SS * CC];            // per-split per-class counts
__device__ int   g_off[SS * CC];            // per-split per-class offsets
__device__ int   g_totcnt[CC];              // global per-class counts

// ---------------------------------------------------------------------------
// Kernel 0: counting sort of labels by class, per split. 1 CTA, trivial cost.
// Deterministic: stable (ascending b within class).
// ---------------------------------------------------------------------------
__global__ void sort_labels_kernel(const int* __restrict__ labels)
{
    __shared__ int slab[BB];
    const int tid = threadIdx.x;

    for (int i = tid; i < BB; i += blockDim.x)
        slab[i] = labels[i];
    __syncthreads();

    if (tid < SS * CC) {
        const int sb = tid / CC;
        const int c  = tid % CC;
        int cnt = 0, off = 0;
        for (int j = 0; j < BPER; ++j) {
            const int l = slab[sb * BPER + j];
            cnt += (l == c);
            off += (l < c);
        }
        g_cnt[sb * CC + c] = cnt;
        g_off[sb * CC + c] = off;
        int k = off;
        for (int j = 0; j < BPER; ++j)
            if (slab[sb * BPER + j] == c)
                g_perm[sb * BPER + (k++)] = j;   // local b within split
    }
    if (tid < CC) {
        int tot = 0;
        for (int j = 0; j < BB; ++j)
            tot += (slab[j] == tid);
        g_totcnt[tid] = tot;
    }
}

// ---------------------------------------------------------------------------
// Stage 1: register-only class accumulation over class-sorted samples.
// Grid: (V/TT, SS). Each thread owns one v; per class segment, a single
// scalar accumulator -> direct store to g_partials. No smem RMW chains.
// ---------------------------------------------------------------------------
__global__ void __launch_bounds__(TT)
attr_accumulate_kernel(const float* __restrict__ sparse,
                       const float* __restrict__ W)
{
    __shared__ int s_perm[BPER];
    __shared__ int s_cnt[CC];
    __shared__ int s_off[CC];

    const int tid = threadIdx.x;
    const int sb  = blockIdx.y;

    if (tid < BPER) s_perm[tid] = g_perm[sb * BPER + tid];
    if (tid < CC) {
        s_cnt[tid] = g_cnt[sb * CC + tid];
        s_off[tid] = g_off[sb * CC + tid];
    }
    __syncthreads();

    const int v = blockIdx.x * TT + tid;
    const float* __restrict__ sp = sparse + (size_t)sb * BPER * VV + v;
    const float* __restrict__ Wp = W + ((size_t)sb * BPER * VV + (size_t)v) * CC;
    float* __restrict__ part = g_partials + (size_t)sb * CC * VV + v;

    #pragma unroll
    for (int c = 0; c < CC; ++c) {
        const int n    = s_cnt[c];
        const int base = s_off[c];
        float acc = 0.0f;
        #pragma unroll 4
        for (int j = 0; j < n; ++j) {
            const int b = s_perm[base + j];
            const float svv = sp[(size_t)b * VV];
            const float wvv = Wp[(size_t)b * VV * CC + c];
            acc += fabsf(svv * wvv);
        }
        part[(size_t)c * VV] = acc;   // zero for absent classes — stage 2 relies on it
    }
}

// ---------------------------------------------------------------------------
// Stage 2: one thread per output element (C*V = 524288 -> 2048 CTAs).
// Reduce SS partials, apply EMA / fresh-copy / no-op branches.
// ---------------------------------------------------------------------------
__global__ void __launch_bounds__(TT)
centroid_finalize_kernel(const float* __restrict__ centroids,
                         const int* __restrict__ initialized,
                         float* __restrict__ out)
{
    const int idx = blockIdx.x * TT + threadIdx.x;   // 0 .. C*V-1
    const int c = idx >> 15;          // VV = 2^15
    // v = idx & (VV-1) is implicit in idx addressing below

    float sum = 0.0f;
    #pragma unroll
    for (int s = 0; s < SS; ++s)
        sum += g_partials[((size_t)s * CC + c) * VV + (idx & (VV - 1))];

    const int   n    = g_totcnt[c];
    const float cen  = centroids[idx];
    const float mean = sum / fmaxf((float)n, 1.0f);

    float o;
    if (n > 0)
        o = (initialized[c] != 0) ? (cen + ALPHA * (mean - cen)) : mean;
    else
        o = cen;

    out[idx] = o;
}

// ---------------------------------------------------------------------------
// Launch: graph-capturable, allocation-free.
// Inputs identified BY ELEMENT COUNT (robust to metadata ordering):
//   W_eff       f32[B,V,C] -> 268435456 elems
//   sparse_vec  f32[B,V]   ->  16777216 elems
//   centroids   f32[C,V]   ->    524288 elems
//   labels      i32[B]     ->       512 elems
//   initialized i32[C]     ->        16 elems (bool widened to int32)
// Output: f32[C,V].
// ---------------------------------------------------------------------------
extern "C" void kernel_launch(void* const* d_in, const int* in_sizes, int n_in,
                              void* d_out, int out_size)
{
    const float* sparse    = nullptr;
    const float* W         = nullptr;
    const int*   labels    = nullptr;
    const float* centroids = nullptr;
    const int*   init      = nullptr;
    float*       out       = (float*)d_out;

    for (int i = 0; i < n_in; ++i) {
        switch (in_sizes[i]) {
            case BB * VV:            sparse    = (const float*)d_in[i]; break; // 16777216
            case BB:                 labels    = (const int*)d_in[i];   break; // 512
            case CC * VV:            centroids = (const float*)d_in[i]; break; // 524288
            case CC:                 init      = (const int*)d_in[i];   break; // 16
            default:                 W         = (const float*)d_in[i]; break; // 268435456
        }
    }

    sort_labels_kernel<<<1, 256>>>(labels);

    dim3 g1(VV / TT, SS);
    attr_accumulate_kernel<<<g1, TT>>>(sparse, W);

    centroid_finalize_kernel<<<(CC * VV) / TT, TT>>>(centroids, init, out);
}

// round 7
// speedup vs baseline: 1.0564x; 1.0268x over previous
#include <cuda_runtime.h>
#include <cstdint>

// Problem constants
#define BB 512
#define VV 32768
#define CC 16
#define SS 8            // B-splits
#define TT 256          // threads per block
#define BPER (BB / SS)  // 64 samples per split

// EMA coefficient: 1 - MOMENTUM = 2/(STEPS_PER_EPOCH+1)
#define ALPHA ((float)(2.0 / 1001.0))

// Partial sums scratch: [S][C][V] fp32 = 16 MB (device global — no allocation)
__device__ float g_partials[SS * CC * VV];

// ---------------------------------------------------------------------------
// Stage 1: per-CTA inline ballot counting-sort of this split's 64 labels
// (warp 0, ~300 cyc), then register-only class accumulation over the sorted
// samples. Grid: (V/TT, SS) = 1024 CTAs. Each thread owns one v.
// ---------------------------------------------------------------------------
__global__ void __launch_bounds__(TT)
attr_accumulate_kernel(const float* __restrict__ sparse,
                       const float* __restrict__ W,
                       const int* __restrict__ labels)
{
    __shared__ int s_perm[BPER];
    __shared__ int s_cnt[CC];
    __shared__ int s_off[CC];

    const int tid = threadIdx.x;
    const int sb  = blockIdx.y;

    if (tid < 32) {
        const int lane = tid;
        const int l0 = labels[sb * BPER + lane];
        const int l1 = labels[sb * BPER + 32 + lane];
        const unsigned lt = (1u << lane) - 1u;
        int base = 0;
        #pragma unroll
        for (int c = 0; c < CC; ++c) {
            const unsigned m0 = __ballot_sync(0xffffffffu, l0 == c);
            const unsigned m1 = __ballot_sync(0xffffffffu, l1 == c);
            const int c0 = __popc(m0), c1 = __popc(m1);
            if (lane == 0) { s_cnt[c] = c0 + c1; s_off[c] = base; }
            if (l0 == c) s_perm[base + __popc(m0 & lt)] = lane;
            if (l1 == c) s_perm[base + c0 + __popc(m1 & lt)] = 32 + lane;
            base += c0 + c1;
        }
    }
    __syncthreads();

    const int v = blockIdx.x * TT + tid;
    const float* __restrict__ sp = sparse + (size_t)sb * BPER * VV + v;
    const float* __restrict__ Wp = W + ((size_t)sb * BPER * VV + (size_t)v) * CC;
    float* __restrict__ part = g_partials + (size_t)sb * CC * VV + v;

    #pragma unroll
    for (int c = 0; c < CC; ++c) {
        const int n    = s_cnt[c];
        const int base = s_off[c];
        float acc = 0.0f;
        #pragma unroll 8
        for (int j = 0; j < n; ++j) {
            const int b = s_perm[base + j];
            const float svv = __ldcs(sp + (size_t)b * VV);
            const float wvv = __ldcs(Wp + (size_t)b * VV * CC + c);
            acc += fabsf(svv * wvv);
        }
        part[(size_t)c * VV] = acc;   // zero for absent classes — stage 2 relies on it
    }
}

// ---------------------------------------------------------------------------
// Stage 2: float4 per thread (C*V/4 = 131072 threads -> 512 CTAs).
// Inline label histogram in the prologue; reduce SS partials; apply
// EMA / fresh-copy / no-op branches.
// ---------------------------------------------------------------------------
__global__ void __launch_bounds__(TT)
centroid_finalize_kernel(const float* __restrict__ centroids,
                         const int* __restrict__ labels,
                         const int* __restrict__ initialized,
                         float* __restrict__ out)
{
    __shared__ int s_tot[CC];
    const int tid = threadIdx.x;

    if (tid < CC) s_tot[tid] = 0;
    __syncthreads();
    {
        const int l0 = labels[tid];
        const int l1 = labels[tid + TT];
        atomicAdd(&s_tot[l0], 1);
        atomicAdd(&s_tot[l1], 1);
    }
    __syncthreads();

    const int idx4 = blockIdx.x * TT + tid;   // float4 index
    const int e0   = idx4 * 4;                // first element index
    const int c    = e0 >> 15;                // VV = 2^15; 4 elems share c
    const int v    = e0 & (VV - 1);

    float4 sum = make_float4(0.f, 0.f, 0.f, 0.f);
    #pragma unroll
    for (int s = 0; s < SS; ++s) {
        const float4 p = *reinterpret_cast<const float4*>(
            g_partials + ((size_t)s * CC + c) * VV + v);
        sum.x += p.x; sum.y += p.y; sum.z += p.z; sum.w += p.w;
    }

    const int   n   = s_tot[c];
    const float inv = 1.0f / fmaxf((float)n, 1.0f);
    const float4 cen = *reinterpret_cast<const float4*>(centroids + e0);

    float4 o;
    if (n > 0) {
        if (initialized[c] != 0) {
            o.x = cen.x + ALPHA * (sum.x * inv - cen.x);
            o.y = cen.y + ALPHA * (sum.y * inv - cen.y);
            o.z = cen.z + ALPHA * (sum.z * inv - cen.z);
            o.w = cen.w + ALPHA * (sum.w * inv - cen.w);
        } else {
            o.x = sum.x * inv; o.y = sum.y * inv;
            o.z = sum.z * inv; o.w = sum.w * inv;
        }
    } else {
        o = cen;
    }

    *reinterpret_cast<float4*>(out + e0) = o;
}

// ---------------------------------------------------------------------------
// Launch: graph-capturable, allocation-free. 2 kernels only.
// Inputs identified BY ELEMENT COUNT (robust to metadata ordering):
//   W_eff       f32[B,V,C] -> 268435456 elems
//   sparse_vec  f32[B,V]   ->  16777216 elems
//   centroids   f32[C,V]   ->    524288 elems
//   labels      i32[B]     ->       512 elems
//   initialized i32[C]     ->        16 elems (bool widened to int32)
// Output: f32[C,V].
// ---------------------------------------------------------------------------
extern "C" void kernel_launch(void* const* d_in, const int* in_sizes, int n_in,
                              void* d_out, int out_size)
{
    const float* sparse    = nullptr;
    const float* W         = nullptr;
    const int*   labels    = nullptr;
    const float* centroids = nullptr;
    const int*   init      = nullptr;
    float*       out       = (float*)d_out;

    for (int i = 0; i < n_in; ++i) {
        switch (in_sizes[i]) {
            case BB * VV:            sparse    = (const float*)d_in[i]; break; // 16777216
            case BB:                 labels    = (const int*)d_in[i];   break; // 512
            case CC * VV:            centroids = (const float*)d_in[i]; break; // 524288
            case CC:                 init      = (const int*)d_in[i];   break; // 16
            default:                 W         = (const float*)d_in[i]; break; // 268435456
        }
    }

    dim3 g1(VV / TT, SS);
    attr_accumulate_kernel<<<g1, TT>>>(sparse, W, labels);

    centroid_finalize_kernel<<<(CC * VV / 4) / TT, TT>>>(centroids, labels, init, out);
}

// round 9
// speedup vs baseline: 1.0904x; 1.0321x over previous
#include <cuda_runtime.h>
#include <cstdint>

// Problem constants
#define BB 512
#define VV 32768
#define CC 16
#define SS 4            // B-splits
#define TT 256          // threads per block
#define BPER (BB / SS)  // 128 samples per split
#define VT (TT / 4)     // 64 v per CTA (4 quad-threads per v)
#define UN 4            // inner unroll

// EMA coefficient: 1 - MOMENTUM = 2/(STEPS_PER_EPOCH+1)
#define ALPHA ((float)(2.0 / 1001.0))

// Partial sums scratch: [S][C][V] fp32 = 8 MB (device global — no allocation)
__device__ float g_partials[SS * CC * VV];

// ---------------------------------------------------------------------------
// Stage 1: fully-coalesced W read. Thread owns (v, quad q); loads float4 of
// W channels 4q..4q+3 every sample (warp = contiguous 512B). A thread only
// accumulates when labels[b]/4 == q, into one of 4 register accumulators
// (classes 4q..4q+3). Grid: (VV/VT, SS) = (512, 4).
// ---------------------------------------------------------------------------
__global__ void __launch_bounds__(TT)
attr_accumulate_kernel(const float* __restrict__ sparse,
                       const float* __restrict__ W,
                       const int* __restrict__ labels)
{
    __shared__ int s_lab[BPER];

    const int tid = threadIdx.x;
    const int sb  = blockIdx.y;

    if (tid < BPER) s_lab[tid] = labels[sb * BPER + tid];
    __syncthreads();

    const int v = blockIdx.x * VT + (tid >> 2);
    const int q = tid & 3;

    const float* __restrict__ Wp = W + ((size_t)(sb * BPER) * VV + v) * CC + 4 * q;
    const float* __restrict__ sp = sparse + (size_t)(sb * BPER) * VV + v;

    float a0 = 0.f, a1 = 0.f, a2 = 0.f, a3 = 0.f;

    for (int b0 = 0; b0 < BPER; b0 += UN) {
        float4 w[UN];
        float  sv[UN];
        int    lr[UN];
        bool   sel[UN];

        // Batch the global loads for MLP: UN unconditional LDG.128 (W stream)
        // + up to UN predicated LDG.32 (sparse).
        #pragma unroll
        for (int j = 0; j < UN; ++j) {
            const int b   = b0 + j;
            const int lab = s_lab[b];
            sel[j] = ((lab >> 2) == q);
            lr[j]  = lab & 3;
            w[j]   = __ldcs(reinterpret_cast<const float4*>(Wp + (size_t)b * VV * CC));
            sv[j]  = 0.f;
            if (sel[j]) sv[j] = __ldcs(sp + (size_t)b * VV);
        }

        #pragma unroll
        for (int j = 0; j < UN; ++j) {
            const int r = lr[j];
            const float ws = (r < 2) ? ((r & 1) ? w[j].y : w[j].x)
                                     : ((r & 1) ? w[j].w : w[j].z);
            const float val = sel[j] ? fabsf(sv[j] * ws) : 0.f;
            a0 += (r == 0) ? val : 0.f;
            a1 += (r == 1) ? val : 0.f;
            a2 += (r == 2) ? val : 0.f;
            a3 += (r == 3) ? val : 0.f;
        }
    }

    // Thread writes its 4 class rows (classes 4q..4q+3) at column v.
    float* __restrict__ part = g_partials + (size_t)sb * CC * VV + (size_t)(4 * q) * VV + v;
    part[0]            = a0;
    part[(size_t)VV]   = a1;
    part[(size_t)2*VV] = a2;
    part[(size_t)3*VV] = a3;
}

// ---------------------------------------------------------------------------
// Stage 2: float2 per thread (C*V/2 threads -> 1024 CTAs). Inline label
// histogram; reduce SS partials (mostly L2-resident); EMA / fresh / no-op.
// ---------------------------------------------------------------------------
__global__ void __launch_bounds__(TT)
centroid_finalize_kernel(const float* __restrict__ centroids,
                         const int* __restrict__ labels,
                         const int* __restrict__ initialized,
                         float* __restrict__ out)
{
    __shared__ int s_tot[CC];
    const int tid = threadIdx.x;

    if (tid < CC) s_tot[tid] = 0;
    __syncthreads();
    {
        const int l0 = labels[tid];
        const int l1 = labels[tid + TT];
        atomicAdd(&s_tot[l0], 1);
        atomicAdd(&s_tot[l1], 1);
    }
    __syncthreads();

    const int idx2 = blockIdx.x * TT + tid;   // float2 index
    const int e0   = idx2 * 2;
    const int c    = e0 >> 15;                // VV = 2^15; both elems share c
    const int v    = e0 & (VV - 1);

    float sx = 0.f, sy = 0.f;
    #pragma unroll
    for (int s = 0; s < SS; ++s) {
        const float2 p = *reinterpret_cast<const float2*>(
            g_partials + ((size_t)s * CC + c) * VV + v);
        sx += p.x; sy += p.y;
    }

    const int   n   = s_tot[c];
    const float inv = 1.0f / fmaxf((float)n, 1.0f);
    const float2 cen = *reinterpret_cast<const float2*>(centroids + e0);

    float2 o;
    if (n > 0) {
        if (initialized[c] != 0) {
            o.x = cen.x + ALPHA * (sx * inv - cen.x);
            o.y = cen.y + ALPHA * (sy * inv - cen.y);
        } else {
            o.x = sx * inv;
            o.y = sy * inv;
        }
    } else {
        o = cen;
    }

    *reinterpret_cast<float2*>(out + e0) = o;
}

// ---------------------------------------------------------------------------
// Launch: graph-capturable, allocation-free. 2 kernels.
// Inputs identified BY ELEMENT COUNT (robust to metadata ordering):
//   W_eff       f32[B,V,C] -> 268435456 elems
//   sparse_vec  f32[B,V]   ->  16777216 elems
//   centroids   f32[C,V]   ->    524288 elems
//   labels      i32[B]     ->       512 elems
//   initialized i32[C]     ->        16 elems (bool widened to int32)
// Output: f32[C,V].
// ---------------------------------------------------------------------------
extern "C" void kernel_launch(void* const* d_in, const int* in_sizes, int n_in,
                              void* d_out, int out_size)
{
    const float* sparse    = nullptr;
    const float* W         = nullptr;
    const int*   labels    = nullptr;
    const float* centroids = nullptr;
    const int*   init      = nullptr;
    float*       out       = (float*)d_out;

    for (int i = 0; i < n_in; ++i) {
        switch (in_sizes[i]) {
            case BB * VV:            sparse    = (const float*)d_in[i]; break; // 16777216
            case BB:                 labels    = (const int*)d_in[i];   break; // 512
            case CC * VV:            centroids = (const float*)d_in[i]; break; // 524288
            case CC:                 init      = (const int*)d_in[i];   break; // 16
            default:                 W         = (const float*)d_in[i]; break; // 268435456
        }
    }

    dim3 g1(VV / VT, SS);
    attr_accumulate_kernel<<<g1, TT>>>(sparse, W, labels);

    centroid_finalize_kernel<<<(CC * VV / 2) / TT, TT>>>(centroids, labels, init, out);
}